// round 4
// baseline (speedup 1.0000x reference)
#include <cuda_runtime.h>
#include <cuda_bf16.h>
#include <math.h>

#define NPTS   8192
#define BATCH  4
#define K      16
#define TPB    128
#define NCELL  512                // 8x8x8 Morton cells
#define CLO    (-5.12f)
#define CW     (1.28f)

// ---------------- scratch (no allocs allowed) ----------------
__device__ float4 g_psort[BATCH * NPTS];   // sorted points: xyz + |p|^2
__device__ int    g_orig [BATCH * NPTS];   // sorted pos -> original index
__device__ int    g_cell [BATCH * NPTS];
__device__ int    g_rank [BATCH * NPTS];
__device__ int    g_hist [BATCH * NCELL];  // counts
__device__ int    g_off  [BATCH * NCELL];  // exclusive offsets

__device__ __forceinline__ int morton3(int x, int y, int z) {
    int m = 0;
#pragma unroll
    for (int i = 0; i < 3; i++) {
        m |= (((x >> i) & 1) << (3 * i))
           | (((y >> i) & 1) << (3 * i + 1))
           | (((z >> i) & 1) << (3 * i + 2));
    }
    return m;
}

__device__ __forceinline__ int cell_of(float px, float py, float pz) {
    const float s = 1.0f / CW;
    int ix = (int)((px - CLO) * s); ix = ix < 0 ? 0 : (ix > 7 ? 7 : ix);
    int iy = (int)((py - CLO) * s); iy = iy < 0 ? 0 : (iy > 7 ? 7 : iy);
    int iz = (int)((pz - CLO) * s); iz = iz < 0 ? 0 : (iz > 7 ? 7 : iz);
    return morton3(ix, iy, iz);
}

// ---------------- pass 0: zero histograms ----------------
__global__ void zero_hist_kernel() {
    g_hist[blockIdx.x * NCELL + threadIdx.x] = 0;
}

// ---------------- pass 1: cell id + rank within cell ----------------
__global__ void cell_kernel(const float* __restrict__ x) {
    const int gi = blockIdx.x * blockDim.x + threadIdx.x;   // 0..B*N-1
    const int b  = gi / NPTS;
    const float px = x[gi * 3 + 0];
    const float py = x[gi * 3 + 1];
    const float pz = x[gi * 3 + 2];
    const int cell = cell_of(px, py, pz);
    const int r = atomicAdd(&g_hist[b * NCELL + cell], 1);
    g_cell[gi] = cell;
    g_rank[gi] = r;
}

// ---------------- pass 2: exclusive scan of 512 bins per batch ----------------
__global__ void scan_kernel() {
    __shared__ int s[NCELL];
    const int b = blockIdx.x, t = threadIdx.x;
    s[t] = g_hist[b * NCELL + t];
    __syncthreads();
    const int own = s[t];
    for (int off = 1; off < NCELL; off <<= 1) {
        int add = (t >= off) ? s[t - off] : 0;
        __syncthreads();
        s[t] += add;
        __syncthreads();
    }
    g_off[b * NCELL + t] = s[t] - own;   // exclusive
}

// ---------------- pass 3: scatter into Morton order ----------------
__global__ void scatter_kernel(const float* __restrict__ x) {
    const int gi = blockIdx.x * blockDim.x + threadIdx.x;
    const int b  = gi / NPTS;
    const int i  = gi - b * NPTS;
    const float px = x[gi * 3 + 0];
    const float py = x[gi * 3 + 1];
    const float pz = x[gi * 3 + 2];
    const int pos = g_off[b * NCELL + g_cell[gi]] + g_rank[gi];
    g_psort[b * NPTS + pos] = make_float4(px, py, pz, px * px + py * py + pz * pz);
    g_orig [b * NPTS + pos] = i;
}

// ---------------- main kernel: cell-pruned exact kNN + eigen ----------------
__global__ __launch_bounds__(TPB)
void eig_ratio_kernel(float* __restrict__ out) {
    __shared__ float2 s_bx[NCELL];   // x lo/hi per cell
    __shared__ float2 s_by[NCELL];
    __shared__ float2 s_bz[NCELL];
    __shared__ int    s_off[NCELL];
    __shared__ int    s_cnt[NCELL];

    const int b   = blockIdx.y;
    const int tid = threadIdx.x;
    const int q   = blockIdx.x * TPB + tid;    // sorted-order query position
    const int bN  = b * NPTS;

    // build cell metadata in smem
    for (int c = tid; c < NCELL; c += TPB) {
        const int ix = ((c >> 0) & 1) | (((c >> 3) & 1) << 1) | (((c >> 6) & 1) << 2);
        const int iy = ((c >> 1) & 1) | (((c >> 4) & 1) << 1) | (((c >> 7) & 1) << 2);
        const int iz = ((c >> 2) & 1) | (((c >> 5) & 1) << 1) | (((c >> 8) & 1) << 2);
        float lx = CLO + CW * ix, hx = lx + CW;
        float ly = CLO + CW * iy, hy = ly + CW;
        float lz = CLO + CW * iz, hz = lz + CW;
        if (ix == 0) lx = -1e30f;  if (ix == 7) hx = 1e30f;
        if (iy == 0) ly = -1e30f;  if (iy == 7) hy = 1e30f;
        if (iz == 0) lz = -1e30f;  if (iz == 7) hz = 1e30f;
        s_bx[c] = make_float2(lx, hx);
        s_by[c] = make_float2(ly, hy);
        s_bz[c] = make_float2(lz, hz);
        s_off[c] = g_off [b * NCELL + c];
        s_cnt[c] = g_hist[b * NCELL + c];
    }
    __syncthreads();

    const float4 qp = g_psort[bN + q];
    const float qx = qp.x, qy = qp.y, qz = qp.z, qsq = qp.w;
    const int own = cell_of(qx, qy, qz);

    float bval[K];
    int   bidx[K];
#pragma unroll
    for (int t = 0; t < K; t++) { bval[t] = 3.4e38f; bidx[t] = 0; }
    float worst = 3.4e38f;

    // scan a cell's point range
    auto scan_range = [&](int beg, int end) {
#pragma unroll 4
        for (int j = beg; j < end; j++) {
            const float4 c = g_psort[bN + j];
            const float dot = qx * c.x + qy * c.y + qz * c.z;
            const float d2  = fmaf(-2.0f, dot, qsq + c.w);
            if (d2 < worst) {
                int ms = 0; float mv = bval[0];
#pragma unroll
                for (int t = 1; t < K; t++)
                    if (bval[t] > mv) { mv = bval[t]; ms = t; }
#pragma unroll
                for (int t = 0; t < K; t++)
                    if (t == ms) { bval[t] = d2; bidx[t] = j; }
                worst = bval[0];
#pragma unroll
                for (int t = 1; t < K; t++) worst = fmaxf(worst, bval[t]);
            }
        }
    };

    // 1) own cell first — tightens the threshold fast
    scan_range(s_off[own], s_off[own] + s_cnt[own]);

    // 2) all other cells with exact box-distance pruning
    for (int c = 0; c < NCELL; c++) {
        const int cnt = s_cnt[c];
        if (cnt == 0 || c == own) continue;
        const float2 bx = s_bx[c], by = s_by[c], bz = s_bz[c];
        const float dx = fmaxf(fmaxf(bx.x - qx, qx - bx.y), 0.0f);
        const float dy = fmaxf(fmaxf(by.x - qy, qy - by.y), 0.0f);
        const float dz = fmaxf(fmaxf(bz.x - qz, qz - bz.y), 0.0f);
        const float md2 = dx * dx + dy * dy + dz * dz;
        if (md2 >= worst) continue;
        const int beg = s_off[c];
        scan_range(beg, beg + cnt);
    }

    // ---- sort 16 ascending by d2 (deterministic, matches reference top_k) ----
#pragma unroll
    for (int pass = 0; pass < K; pass++) {
#pragma unroll
        for (int t = (pass & 1); t + 1 < K; t += 2) {
            if (bval[t] > bval[t + 1]) {
                float tv = bval[t]; bval[t] = bval[t + 1]; bval[t + 1] = tv;
                int   ti = bidx[t]; bidx[t] = bidx[t + 1]; bidx[t + 1] = ti;
            }
        }
    }

    // ---- gather neighbors, covariance (fp32, same as reference) ----
    float nx[K], ny[K], nz[K];
#pragma unroll
    for (int t = 0; t < K; t++) {
        const float4 np = g_psort[bN + bidx[t]];
        nx[t] = np.x; ny[t] = np.y; nz[t] = np.z;
    }
    float mx = 0.f, my = 0.f, mz = 0.f;
#pragma unroll
    for (int t = 0; t < K; t++) { mx += nx[t]; my += ny[t]; mz += nz[t]; }
    const float invk = 1.0f / (float)K;
    mx *= invk; my *= invk; mz *= invk;

    float c00 = 0.f, c01 = 0.f, c02 = 0.f, c11 = 0.f, c12 = 0.f, c22 = 0.f;
#pragma unroll
    for (int t = 0; t < K; t++) {
        const float dx = nx[t] - mx, dy = ny[t] - my, dz = nz[t] - mz;
        c00 += dx * dx; c01 += dx * dy; c02 += dx * dz;
        c11 += dy * dy; c12 += dy * dz; c22 += dz * dz;
    }

    // ---- 3x3 symmetric eigenvalues, trigonometric closed form (fp64) ----
    const double a00 = (double)(c00 * invk);
    const double a01 = (double)(c01 * invk);
    const double a02 = (double)(c02 * invk);
    const double a11 = (double)(c11 * invk);
    const double a12 = (double)(c12 * invk);
    const double a22 = (double)(c22 * invk);

    const double qm = (a00 + a11 + a22) / 3.0;
    const double p1 = a01 * a01 + a02 * a02 + a12 * a12;
    const double d0 = a00 - qm, d1 = a11 - qm, d2e = a22 - qm;
    const double p2 = d0 * d0 + d1 * d1 + d2e * d2e + 2.0 * p1;

    double ratio;
    if (p2 <= 0.0) {
        ratio = 1.0;
    } else {
        const double pp  = sqrt(p2 / 6.0);
        const double inv = 1.0 / pp;
        const double b00 = d0 * inv, b11 = d1 * inv, b22 = d2e * inv;
        const double b01 = a01 * inv, b02 = a02 * inv, b12 = a12 * inv;
        const double detB = b00 * (b11 * b22 - b12 * b12)
                          - b01 * (b01 * b22 - b12 * b02)
                          + b02 * (b01 * b12 - b11 * b02);
        double r = 0.5 * detB;
        r = fmin(1.0, fmax(-1.0, r));
        const double phi = acos(r) / 3.0;
        const double e_big   = qm + 2.0 * pp * cos(phi);
        const double e_small = qm + 2.0 * pp * cos(phi + 2.0943951023931953);
        const double e_mid   = 3.0 * qm - e_big - e_small;
        ratio = e_big / e_mid;
    }

    out[bN + g_orig[bN + q]] = (float)ratio;
}

extern "C" void kernel_launch(void* const* d_in, const int* in_sizes, int n_in,
                              void* d_out, int out_size) {
    const float* x = (const float*)d_in[0];   // (4, 8192, 3) fp32
    float* out = (float*)d_out;               // (4, 8192) fp32

    zero_hist_kernel<<<BATCH, NCELL>>>();
    cell_kernel<<<(BATCH * NPTS) / 256, 256>>>(x);
    scan_kernel<<<BATCH, NCELL>>>();
    scatter_kernel<<<(BATCH * NPTS) / 256, 256>>>(x);

    dim3 grid(NPTS / TPB, BATCH);
    eig_ratio_kernel<<<grid, TPB>>>(out);
}

// round 5
// speedup vs baseline: 2.0253x; 2.0253x over previous
#include <cuda_runtime.h>
#include <cuda_bf16.h>
#include <math.h>

#define NPTS   8192
#define BATCH  4
#define K      16
#define TPB    128
#define NCELL  512                // 8x8x8 Morton cells
#define CLO    (-5.12f)
#define CW     (1.28f)

// ---------------- scratch (no allocs allowed) ----------------
__device__ float4 g_psort[BATCH * NPTS];   // sorted points: xyz + |p|^2
__device__ int    g_orig [BATCH * NPTS];   // sorted pos -> original index
__device__ int    g_cell [BATCH * NPTS];
__device__ int    g_rank [BATCH * NPTS];
__device__ int    g_hist [BATCH * NCELL];  // counts
__device__ int    g_off  [BATCH * NCELL];  // exclusive offsets

__device__ __forceinline__ int morton3(int x, int y, int z) {
    int m = 0;
#pragma unroll
    for (int i = 0; i < 3; i++) {
        m |= (((x >> i) & 1) << (3 * i))
           | (((y >> i) & 1) << (3 * i + 1))
           | (((z >> i) & 1) << (3 * i + 2));
    }
    return m;
}

__device__ __forceinline__ int clamp8(int v) {
    return v < 0 ? 0 : (v > 7 ? 7 : v);
}

// ---------------- pass 0: zero histograms ----------------
__global__ void zero_hist_kernel() {
    g_hist[blockIdx.x * NCELL + threadIdx.x] = 0;
}

// ---------------- pass 1: cell id + rank within cell ----------------
__global__ void cell_kernel(const float* __restrict__ x) {
    const int gi = blockIdx.x * blockDim.x + threadIdx.x;   // 0..B*N-1
    const int b  = gi / NPTS;
    const float px = x[gi * 3 + 0];
    const float py = x[gi * 3 + 1];
    const float pz = x[gi * 3 + 2];
    const float s = 1.0f / CW;
    const int ix = clamp8((int)((px - CLO) * s));
    const int iy = clamp8((int)((py - CLO) * s));
    const int iz = clamp8((int)((pz - CLO) * s));
    const int cell = morton3(ix, iy, iz);
    const int r = atomicAdd(&g_hist[b * NCELL + cell], 1);
    g_cell[gi] = cell;
    g_rank[gi] = r;
}

// ---------------- pass 2: exclusive scan of 512 bins per batch ----------------
__global__ void scan_kernel() {
    __shared__ int s[NCELL];
    const int b = blockIdx.x, t = threadIdx.x;
    s[t] = g_hist[b * NCELL + t];
    __syncthreads();
    const int own = s[t];
    for (int off = 1; off < NCELL; off <<= 1) {
        int add = (t >= off) ? s[t - off] : 0;
        __syncthreads();
        s[t] += add;
        __syncthreads();
    }
    g_off[b * NCELL + t] = s[t] - own;   // exclusive
}

// ---------------- pass 3: scatter into Morton order ----------------
__global__ void scatter_kernel(const float* __restrict__ x) {
    const int gi = blockIdx.x * blockDim.x + threadIdx.x;
    const int b  = gi / NPTS;
    const int i  = gi - b * NPTS;
    const float px = x[gi * 3 + 0];
    const float py = x[gi * 3 + 1];
    const float pz = x[gi * 3 + 2];
    const int pos = g_off[b * NCELL + g_cell[gi]] + g_rank[gi];
    g_psort[b * NPTS + pos] = make_float4(px, py, pz, px * px + py * py + pz * pz);
    g_orig [b * NPTS + pos] = i;
}

// ---------------- main kernel: shell-ordered exact kNN + eigen ----------------
__global__ __launch_bounds__(TPB)
void eig_ratio_kernel(float* __restrict__ out) {
    __shared__ int s_off[NCELL];
    __shared__ int s_cnt[NCELL];

    const int b   = blockIdx.y;
    const int tid = threadIdx.x;
    const int q   = blockIdx.x * TPB + tid;    // sorted-order query position
    const int bN  = b * NPTS;

    for (int c = tid; c < NCELL; c += TPB) {
        s_off[c] = g_off [b * NCELL + c];
        s_cnt[c] = g_hist[b * NCELL + c];
    }
    __syncthreads();

    const float4 qp = g_psort[bN + q];
    const float qx = qp.x, qy = qp.y, qz = qp.z, qsq = qp.w;
    const float s = 1.0f / CW;
    const int cx = clamp8((int)((qx - CLO) * s));
    const int cy = clamp8((int)((qy - CLO) * s));
    const int cz = clamp8((int)((qz - CLO) * s));

    float bval[K];
    int   bidx[K];
#pragma unroll
    for (int t = 0; t < K; t++) { bval[t] = 3.4e38f; bidx[t] = 0; }
    float worst = 3.4e38f;

    auto scan_cell = [&](int cellId) {
        const int beg = s_off[cellId];
        const int end = beg + s_cnt[cellId];
#pragma unroll 4
        for (int j = beg; j < end; j++) {
            const float4 c = g_psort[bN + j];
            const float dot = qx * c.x + qy * c.y + qz * c.z;
            const float d2  = fmaf(-2.0f, dot, qsq + c.w);
            if (d2 < worst) {
                int ms = 0; float mv = bval[0];
#pragma unroll
                for (int t = 1; t < K; t++)
                    if (bval[t] > mv) { mv = bval[t]; ms = t; }
#pragma unroll
                for (int t = 0; t < K; t++)
                    if (t == ms) { bval[t] = d2; bidx[t] = j; }
                worst = bval[0];
#pragma unroll
                for (int t = 1; t < K; t++) worst = fmaxf(worst, bval[t]);
            }
        }
    };

    // ring 0: own cell — converges the threshold fast
    scan_cell(morton3(cx, cy, cz));

    // rings r = 1..7, Chebyshev shells around own cell.
    // Any cell in ring r has box-distance >= (r-1)*CW from the query
    // (holds even for coordinate-clamped outliers, since edge cells
    // extend to infinity), so we can stop once ((r-1)*CW)^2 >= worst.
    for (int r = 1; r <= 7; r++) {
        const float ringmin = (float)(r - 1) * CW;
        if (ringmin * ringmin >= worst) break;
        for (int dz = -r; dz <= r; dz++) {
            const int iz = cz + dz;
            if ((unsigned)iz > 7u) continue;
            // z box distance (extended at edges)
            float lz = CLO + CW * iz, hz = lz + CW;
            if (iz == 0) lz = -1e30f;  if (iz == 7) hz = 1e30f;
            const float ddz = fmaxf(fmaxf(lz - qz, qz - hz), 0.0f);
            const float zz = ddz * ddz;
            for (int dy = -r; dy <= r; dy++) {
                const int iy = cy + dy;
                if ((unsigned)iy > 7u) continue;
                const bool edge_zy = (dz == -r || dz == r || dy == -r || dy == r);
                float ly = CLO + CW * iy, hy = ly + CW;
                if (iy == 0) ly = -1e30f;  if (iy == 7) hy = 1e30f;
                const float ddy = fmaxf(fmaxf(ly - qy, qy - hy), 0.0f);
                const float zy = zz + ddy * ddy;
                for (int dx = -r; dx <= r; dx++) {
                    // only ring-r surface cells (inner cube already scanned)
                    if (!edge_zy && dx != -r && dx != r) continue;
                    const int ix = cx + dx;
                    if ((unsigned)ix > 7u) continue;
                    float lx = CLO + CW * ix, hx = lx + CW;
                    if (ix == 0) lx = -1e30f;  if (ix == 7) hx = 1e30f;
                    const float ddx = fmaxf(fmaxf(lx - qx, qx - hx), 0.0f);
                    const float md2 = zy + ddx * ddx;
                    if (md2 >= worst) continue;
                    const int cellId = morton3(ix, iy, iz);
                    if (s_cnt[cellId] == 0) continue;
                    scan_cell(cellId);
                }
            }
        }
    }

    // ---- sort 16 ascending by d2 (deterministic, matches reference top_k) ----
#pragma unroll
    for (int pass = 0; pass < K; pass++) {
#pragma unroll
        for (int t = (pass & 1); t + 1 < K; t += 2) {
            if (bval[t] > bval[t + 1]) {
                float tv = bval[t]; bval[t] = bval[t + 1]; bval[t + 1] = tv;
                int   ti = bidx[t]; bidx[t] = bidx[t + 1]; bidx[t + 1] = ti;
            }
        }
    }

    // ---- gather neighbors, covariance (fp32, same as reference) ----
    float nx[K], ny[K], nz[K];
#pragma unroll
    for (int t = 0; t < K; t++) {
        const float4 np = g_psort[bN + bidx[t]];
        nx[t] = np.x; ny[t] = np.y; nz[t] = np.z;
    }
    float mx = 0.f, my = 0.f, mz = 0.f;
#pragma unroll
    for (int t = 0; t < K; t++) { mx += nx[t]; my += ny[t]; mz += nz[t]; }
    const float invk = 1.0f / (float)K;
    mx *= invk; my *= invk; mz *= invk;

    float c00 = 0.f, c01 = 0.f, c02 = 0.f, c11 = 0.f, c12 = 0.f, c22 = 0.f;
#pragma unroll
    for (int t = 0; t < K; t++) {
        const float dx = nx[t] - mx, dy = ny[t] - my, dz = nz[t] - mz;
        c00 += dx * dx; c01 += dx * dy; c02 += dx * dz;
        c11 += dy * dy; c12 += dy * dz; c22 += dz * dz;
    }

    // ---- 3x3 symmetric eigenvalues, trigonometric closed form (fp64) ----
    const double a00 = (double)(c00 * invk);
    const double a01 = (double)(c01 * invk);
    const double a02 = (double)(c02 * invk);
    const double a11 = (double)(c11 * invk);
    const double a12 = (double)(c12 * invk);
    const double a22 = (double)(c22 * invk);

    const double qm = (a00 + a11 + a22) / 3.0;
    const double p1 = a01 * a01 + a02 * a02 + a12 * a12;
    const double d0 = a00 - qm, d1 = a11 - qm, d2e = a22 - qm;
    const double p2 = d0 * d0 + d1 * d1 + d2e * d2e + 2.0 * p1;

    double ratio;
    if (p2 <= 0.0) {
        ratio = 1.0;
    } else {
        const double pp  = sqrt(p2 / 6.0);
        const double inv = 1.0 / pp;
        const double b00 = d0 * inv, b11 = d1 * inv, b22 = d2e * inv;
        const double b01 = a01 * inv, b02 = a02 * inv, b12 = a12 * inv;
        const double detB = b00 * (b11 * b22 - b12 * b12)
                          - b01 * (b01 * b22 - b12 * b02)
                          + b02 * (b01 * b12 - b11 * b02);
        double r = 0.5 * detB;
        r = fmin(1.0, fmax(-1.0, r));
        const double phi = acos(r) / 3.0;
        const double e_big   = qm + 2.0 * pp * cos(phi);
        const double e_small = qm + 2.0 * pp * cos(phi + 2.0943951023931953);
        const double e_mid   = 3.0 * qm - e_big - e_small;
        ratio = e_big / e_mid;
    }

    out[bN + g_orig[bN + q]] = (float)ratio;
}

extern "C" void kernel_launch(void* const* d_in, const int* in_sizes, int n_in,
                              void* d_out, int out_size) {
    const float* x = (const float*)d_in[0];   // (4, 8192, 3) fp32
    float* out = (float*)d_out;               // (4, 8192) fp32

    zero_hist_kernel<<<BATCH, NCELL>>>();
    cell_kernel<<<(BATCH * NPTS) / 256, 256>>>(x);
    scan_kernel<<<BATCH, NCELL>>>();
    scatter_kernel<<<(BATCH * NPTS) / 256, 256>>>(x);

    dim3 grid(NPTS / TPB, BATCH);
    eig_ratio_kernel<<<grid, TPB>>>(out);
}

// round 6
// speedup vs baseline: 3.0924x; 1.5269x over previous
#include <cuda_runtime.h>
#include <cuda_bf16.h>
#include <math.h>

#define NPTS   8192
#define BATCH  4
#define K      16
#define TPB    64
#define NG     16                 // cells per axis
#define NCELL  (NG*NG*NG)         // 4096
#define CLO    (-5.12f)
#define CW     (0.64f)

// ---------------- scratch (no allocs allowed) ----------------
__device__ float4 g_psort[BATCH * NPTS];   // sorted points: xyz + |p|^2
__device__ int    g_orig [BATCH * NPTS];   // sorted pos -> original index
__device__ int    g_cellid[BATCH * NPTS];
__device__ int    g_rank [BATCH * NPTS];
__device__ int    g_hist [BATCH * NCELL];  // counts
__device__ int    g_off  [BATCH * NCELL];  // exclusive offsets

__device__ __forceinline__ int morton3_4(int x, int y, int z) {
    int m = 0;
#pragma unroll
    for (int i = 0; i < 4; i++) {
        m |= (((x >> i) & 1) << (3 * i))
           | (((y >> i) & 1) << (3 * i + 1))
           | (((z >> i) & 1) << (3 * i + 2));
    }
    return m;
}

__device__ __forceinline__ int clampg(int v) {
    return v < 0 ? 0 : (v > NG - 1 ? NG - 1 : v);
}

// ---------------- pass 0: zero histograms ----------------
__global__ void zero_hist_kernel() {
    g_hist[blockIdx.x * 1024 + threadIdx.x] = 0;
}

// ---------------- pass 1: cell id + rank within cell ----------------
__global__ void cell_kernel(const float* __restrict__ x) {
    const int gi = blockIdx.x * blockDim.x + threadIdx.x;   // 0..B*N-1
    const int b  = gi / NPTS;
    const float px = x[gi * 3 + 0];
    const float py = x[gi * 3 + 1];
    const float pz = x[gi * 3 + 2];
    const float s = 1.0f / CW;
    const int ix = clampg((int)((px - CLO) * s));
    const int iy = clampg((int)((py - CLO) * s));
    const int iz = clampg((int)((pz - CLO) * s));
    const int cell = morton3_4(ix, iy, iz);
    const int r = atomicAdd(&g_hist[b * NCELL + cell], 1);
    g_cellid[gi] = cell;
    g_rank[gi] = r;
}

// ---------------- pass 2: exclusive scan of 4096 bins per batch ----------------
__global__ void scan_kernel() {
    __shared__ int s[1024];
    const int b = blockIdx.x, t = threadIdx.x;
    const int base = b * NCELL + t * 4;
    int v0 = g_hist[base + 0], v1 = g_hist[base + 1];
    int v2 = g_hist[base + 2], v3 = g_hist[base + 3];
    const int tot = v0 + v1 + v2 + v3;
    s[t] = tot;
    __syncthreads();
    for (int off = 1; off < 1024; off <<= 1) {
        int add = (t >= off) ? s[t - off] : 0;
        __syncthreads();
        s[t] += add;
        __syncthreads();
    }
    int run = s[t] - tot;   // exclusive base for this thread's 4 bins
    g_off[base + 0] = run;  run += v0;
    g_off[base + 1] = run;  run += v1;
    g_off[base + 2] = run;  run += v2;
    g_off[base + 3] = run;
}

// ---------------- pass 3: scatter into Morton order ----------------
__global__ void scatter_kernel(const float* __restrict__ x) {
    const int gi = blockIdx.x * blockDim.x + threadIdx.x;
    const int b  = gi / NPTS;
    const int i  = gi - b * NPTS;
    const float px = x[gi * 3 + 0];
    const float py = x[gi * 3 + 1];
    const float pz = x[gi * 3 + 2];
    const int pos = g_off[b * NCELL + g_cellid[gi]] + g_rank[gi];
    g_psort[b * NPTS + pos] = make_float4(px, py, pz, px * px + py * py + pz * pz);
    g_orig [b * NPTS + pos] = i;
}

// ---------------- main kernel: shell-ordered exact kNN + eigen ----------------
__global__ __launch_bounds__(TPB)
void eig_ratio_kernel(float* __restrict__ out) {
    const int b   = blockIdx.y;
    const int tid = threadIdx.x;
    const int q   = blockIdx.x * TPB + tid;    // sorted-order query position
    const int bN  = b * NPTS;
    const int* __restrict__ offp = g_off  + b * NCELL;
    const int* __restrict__ cntp = g_hist + b * NCELL;

    const float4 qp = g_psort[bN + q];
    const float qx = qp.x, qy = qp.y, qz = qp.z, qsq = qp.w;
    const float s = 1.0f / CW;
    const int cx = clampg((int)((qx - CLO) * s));
    const int cy = clampg((int)((qy - CLO) * s));
    const int cz = clampg((int)((qz - CLO) * s));

    float bval[K];
    int   bidx[K];
#pragma unroll
    for (int t = 0; t < K; t++) { bval[t] = 3.4e38f; bidx[t] = 0; }
    float worst = 3.4e38f;

    auto scan_cell = [&](int cellId) {
        const int beg = __ldg(offp + cellId);
        const int end = beg + __ldg(cntp + cellId);
#pragma unroll 4
        for (int j = beg; j < end; j++) {
            const float4 c = g_psort[bN + j];
            const float dot = qx * c.x + qy * c.y + qz * c.z;
            const float d2  = fmaf(-2.0f, dot, qsq + c.w);
            if (d2 < worst) {
                int ms = 0; float mv = bval[0];
#pragma unroll
                for (int t = 1; t < K; t++)
                    if (bval[t] > mv) { mv = bval[t]; ms = t; }
#pragma unroll
                for (int t = 0; t < K; t++)
                    if (t == ms) { bval[t] = d2; bidx[t] = j; }
                worst = bval[0];
#pragma unroll
                for (int t = 1; t < K; t++) worst = fmaxf(worst, bval[t]);
            }
        }
    };

    // ring 0: own cell — converges the threshold fast
    scan_cell(morton3_4(cx, cy, cz));

    // rings r = 1..NG-1, Chebyshev shells around own cell.
    // Any cell in ring r is separated from the query by (r-1) full-width
    // cells along some axis (holds for clamped outliers too, since edge
    // cells extend to infinity), so stop once ((r-1)*CW)^2 >= worst.
    for (int r = 1; r <= NG - 1; r++) {
        const float ringmin = (float)(r - 1) * CW;
        if (ringmin * ringmin >= worst) break;
        const int zlo = cz - r < 0 ? -cz + 0 : -r;          // dz bounds
        for (int dz = -r; dz <= r; dz++) {
            const int iz = cz + dz;
            if ((unsigned)iz > (unsigned)(NG - 1)) continue;
            float lz = CLO + CW * iz, hz = lz + CW;
            if (iz == 0) lz = -1e30f;  if (iz == NG - 1) hz = 1e30f;
            const float ddz = fmaxf(fmaxf(lz - qz, qz - hz), 0.0f);
            const float zz = ddz * ddz;
            if (zz >= worst) continue;
            for (int dy = -r; dy <= r; dy++) {
                const int iy = cy + dy;
                if ((unsigned)iy > (unsigned)(NG - 1)) continue;
                const bool edge_zy = (dz == -r || dz == r || dy == -r || dy == r);
                float ly = CLO + CW * iy, hy = ly + CW;
                if (iy == 0) ly = -1e30f;  if (iy == NG - 1) hy = 1e30f;
                const float ddy = fmaxf(fmaxf(ly - qy, qy - hy), 0.0f);
                const float zy = zz + ddy * ddy;
                if (zy >= worst) continue;
                const int step = edge_zy ? 1 : 2 * r;
                for (int dx = -r; dx <= r; dx += step) {
                    const int ix = cx + dx;
                    if ((unsigned)ix > (unsigned)(NG - 1)) continue;
                    float lx = CLO + CW * ix, hx = lx + CW;
                    if (ix == 0) lx = -1e30f;  if (ix == NG - 1) hx = 1e30f;
                    const float ddx = fmaxf(fmaxf(lx - qx, qx - hx), 0.0f);
                    const float md2 = zy + ddx * ddx;
                    if (md2 >= worst) continue;
                    scan_cell(morton3_4(ix, iy, iz));
                }
            }
        }
        (void)zlo;
    }

    // ---- sort 16 ascending by d2 (deterministic, matches reference top_k) ----
#pragma unroll
    for (int pass = 0; pass < K; pass++) {
#pragma unroll
        for (int t = (pass & 1); t + 1 < K; t += 2) {
            if (bval[t] > bval[t + 1]) {
                float tv = bval[t]; bval[t] = bval[t + 1]; bval[t + 1] = tv;
                int   ti = bidx[t]; bidx[t] = bidx[t + 1]; bidx[t + 1] = ti;
            }
        }
    }

    // ---- gather neighbors, covariance (fp32, same as reference) ----
    float nx[K], ny[K], nz[K];
#pragma unroll
    for (int t = 0; t < K; t++) {
        const float4 np = g_psort[bN + bidx[t]];
        nx[t] = np.x; ny[t] = np.y; nz[t] = np.z;
    }
    float mx = 0.f, my = 0.f, mz = 0.f;
#pragma unroll
    for (int t = 0; t < K; t++) { mx += nx[t]; my += ny[t]; mz += nz[t]; }
    const float invk = 1.0f / (float)K;
    mx *= invk; my *= invk; mz *= invk;

    float c00 = 0.f, c01 = 0.f, c02 = 0.f, c11 = 0.f, c12 = 0.f, c22 = 0.f;
#pragma unroll
    for (int t = 0; t < K; t++) {
        const float dx = nx[t] - mx, dy = ny[t] - my, dz = nz[t] - mz;
        c00 += dx * dx; c01 += dx * dy; c02 += dx * dz;
        c11 += dy * dy; c12 += dy * dz; c22 += dz * dz;
    }

    // ---- 3x3 symmetric eigenvalues, trigonometric closed form (fp64) ----
    const double a00 = (double)(c00 * invk);
    const double a01 = (double)(c01 * invk);
    const double a02 = (double)(c02 * invk);
    const double a11 = (double)(c11 * invk);
    const double a12 = (double)(c12 * invk);
    const double a22 = (double)(c22 * invk);

    const double qm = (a00 + a11 + a22) / 3.0;
    const double p1 = a01 * a01 + a02 * a02 + a12 * a12;
    const double d0 = a00 - qm, d1 = a11 - qm, d2e = a22 - qm;
    const double p2 = d0 * d0 + d1 * d1 + d2e * d2e + 2.0 * p1;

    double ratio;
    if (p2 <= 0.0) {
        ratio = 1.0;
    } else {
        const double pp  = sqrt(p2 / 6.0);
        const double inv = 1.0 / pp;
        const double b00 = d0 * inv, b11 = d1 * inv, b22 = d2e * inv;
        const double b01 = a01 * inv, b02 = a02 * inv, b12 = a12 * inv;
        const double detB = b00 * (b11 * b22 - b12 * b12)
                          - b01 * (b01 * b22 - b12 * b02)
                          + b02 * (b01 * b12 - b11 * b02);
        double r = 0.5 * detB;
        r = fmin(1.0, fmax(-1.0, r));
        const double phi = acos(r) / 3.0;
        const double e_big   = qm + 2.0 * pp * cos(phi);
        const double e_small = qm + 2.0 * pp * cos(phi + 2.0943951023931953);
        const double e_mid   = 3.0 * qm - e_big - e_small;
        ratio = e_big / e_mid;
    }

    out[bN + g_orig[bN + q]] = (float)ratio;
}

extern "C" void kernel_launch(void* const* d_in, const int* in_sizes, int n_in,
                              void* d_out, int out_size) {
    const float* x = (const float*)d_in[0];   // (4, 8192, 3) fp32
    float* out = (float*)d_out;               // (4, 8192) fp32

    zero_hist_kernel<<<(BATCH * NCELL) / 1024, 1024>>>();
    cell_kernel<<<(BATCH * NPTS) / 256, 256>>>(x);
    scan_kernel<<<BATCH, 1024>>>();
    scatter_kernel<<<(BATCH * NPTS) / 256, 256>>>(x);

    dim3 grid(NPTS / TPB, BATCH);
    eig_ratio_kernel<<<grid, TPB>>>(out);
}